// round 2
// baseline (speedup 1.0000x reference)
#include <cuda_runtime.h>
#include <cstdint>
#include <cstddef>

#define SEQ  4096
#define HID  1024
#define G4   4096
#define NCTA 128
#define SCAN_THREADS 256

typedef unsigned long long ull;

// ---------------- persistent device scratch (static: allocation-free) ----------
__device__ float g_xg[(size_t)SEQ * G4];   // 64 MB: precomputed input-side gates
__device__ float g_hbuf[2][HID];           // double-buffered hidden state
__device__ int   g_counter;                // grid barrier counter (reset by GEMM)

// ---------------- packed f32x2 helpers ----------------------------------------
__device__ __forceinline__ ull pk2(float x, float y) {
  ull r; asm("mov.b64 %0, {%1, %2};" : "=l"(r) : "f"(x), "f"(y)); return r;
}
__device__ __forceinline__ void upk2(ull v, float& x, float& y) {
  asm("mov.b64 {%0, %1}, %2;" : "=f"(x), "=f"(y) : "l"(v));
}
__device__ __forceinline__ void fma2(ull& d, ull a, ull b) {
  asm("fma.rn.f32x2 %0, %1, %2, %0;" : "+l"(d) : "l"(a), "l"(b));
}

__device__ __forceinline__ float sigm(float x) {
  return __fdividef(1.0f, 1.0f + __expf(-x));
}
__device__ __forceinline__ float tanh_(float x) {
  float e = __expf(2.0f * x);
  return 1.0f - __fdividef(2.0f, e + 1.0f);
}

// ==============================================================================
// Kernel 1: xg[m][n] = sum_k emb[inputs[m]][k] * W_ih[n][k] + b_ih[n] + b_hh[n]
// 128x128 tile, BK=8, 256 threads, 8x8 micro-tile via fma.rn.f32x2.
// Also resets the scan barrier counter (stream-ordered before the scan).
// ==============================================================================
__global__ __launch_bounds__(256, 2) void xg_gemm(
    const int*   __restrict__ inputs,
    const float* __restrict__ emb,
    const float* __restrict__ Wih,
    const float* __restrict__ b_ih,
    const float* __restrict__ b_hh)
{
  if (blockIdx.x == 0 && blockIdx.y == 0 && threadIdx.x == 0) g_counter = 0;

  __shared__ __align__(16) float As[8][128];
  __shared__ __align__(16) float Bs[8][128];
  __shared__ int idx[128];

  const int tid = threadIdx.x;
  const int m0 = blockIdx.y << 7;
  const int n0 = blockIdx.x << 7;

  if (tid < 128) idx[tid] = inputs[m0 + tid];
  __syncthreads();

  const int lr = tid >> 1;           // 0..127 row for cooperative loads
  const int lk = (tid & 1) << 2;     // k offset 0 or 4
  const int tx = tid & 15;           // micro-tile col group
  const int ty = tid >> 4;           // micro-tile row group

  const float* aptr = emb + (size_t)idx[lr] * 1024 + lk;
  const float* bptr = Wih + (size_t)(n0 + lr) * 1024 + lk;

  ull acc2[8][4];
  #pragma unroll
  for (int i = 0; i < 8; ++i)
    #pragma unroll
    for (int p = 0; p < 4; ++p) acc2[i][p] = 0ULL;

  for (int k0 = 0; k0 < 1024; k0 += 8) {
    float4 av = *(const float4*)(aptr + k0);
    float4 bv = *(const float4*)(bptr + k0);
    __syncthreads();
    As[lk + 0][lr] = av.x; As[lk + 1][lr] = av.y;
    As[lk + 2][lr] = av.z; As[lk + 3][lr] = av.w;
    Bs[lk + 0][lr] = bv.x; Bs[lk + 1][lr] = bv.y;
    Bs[lk + 2][lr] = bv.z; Bs[lk + 3][lr] = bv.w;
    __syncthreads();

    #pragma unroll
    for (int kk = 0; kk < 8; ++kk) {
      float4 a0 = *(const float4*)&As[kk][ty << 3];
      float4 a1 = *(const float4*)&As[kk][(ty << 3) + 4];
      float4 b0 = *(const float4*)&Bs[kk][tx << 3];
      float4 b1 = *(const float4*)&Bs[kk][(tx << 3) + 4];
      ull bq[4];
      bq[0] = pk2(b0.x, b0.y); bq[1] = pk2(b0.z, b0.w);
      bq[2] = pk2(b1.x, b1.y); bq[3] = pk2(b1.z, b1.w);
      float a[8] = {a0.x, a0.y, a0.z, a0.w, a1.x, a1.y, a1.z, a1.w};
      #pragma unroll
      for (int i = 0; i < 8; ++i) {
        ull ad = pk2(a[i], a[i]);
        #pragma unroll
        for (int p = 0; p < 4; ++p) fma2(acc2[i][p], ad, bq[p]);
      }
    }
  }

  // epilogue: + (b_ih + b_hh), store float4s
  float bias[8];
  #pragma unroll
  for (int p = 0; p < 8; ++p) {
    int n = n0 + (tx << 3) + p;
    bias[p] = b_ih[n] + b_hh[n];
  }
  #pragma unroll
  for (int i = 0; i < 8; ++i) {
    float c[8];
    #pragma unroll
    for (int p = 0; p < 4; ++p) upk2(acc2[i][p], c[2 * p], c[2 * p + 1]);
    #pragma unroll
    for (int p = 0; p < 8; ++p) c[p] += bias[p];
    int m = m0 + (ty << 3) + i;
    float* outp = g_xg + (size_t)m * G4 + n0 + (tx << 3);
    *(float4*)(outp)     = make_float4(c[0], c[1], c[2], c[3]);
    *(float4*)(outp + 4) = make_float4(c[4], c[5], c[6], c[7]);
  }
}

// ==============================================================================
// Kernel 2: persistent LSTM scan. 128 CTAs (all co-resident), 256 threads each.
// CTA b owns h columns j in [8b, 8b+8): 32 rows of W_hh register-resident.
// Warp w handles j = 8b + w: rows {j, j+1024, j+2048, j+3072}.
// Per lane: 16 f32x2 weight pairs per row (cols 2*(lane+32i), +1).
// ==============================================================================
__global__ __launch_bounds__(SCAN_THREADS, 1) void lstm_scan(
    const float* __restrict__ W_hh,
    const float* __restrict__ h0,
    const float* __restrict__ c0)
{
  const int tid  = threadIdx.x;
  const int lane = tid & 31;
  const int w    = tid >> 5;                  // warp 0..7
  const int j    = (blockIdx.x << 3) + w;     // 0..1023

  __shared__ __align__(16) float sh_h[HID];

  // load this thread's 128 weights (as 64 f32x2 pairs) into registers
  ull wreg[4][16];
  #pragma unroll
  for (int g = 0; g < 4; ++g) {
    const float* wp = W_hh + (size_t)(j + (g << 10)) * HID;
    #pragma unroll
    for (int i = 0; i < 16; ++i) {
      float2 v = *(const float2*)(wp + 2 * (lane + 32 * i));
      wreg[g][i] = pk2(v.x, v.y);
    }
  }
  float c = c0[j];   // replicated across lanes (identical updates keep it consistent)

  for (int t = 0; t < SEQ; ++t) {
    // prefetch this step's input-side gate values early (hides DRAM/L2 latency
    // behind the barrier wait)
    float xgv = 0.0f;
    if (lane < 4) xgv = __ldg(g_xg + (size_t)t * G4 + j + (lane << 10));

    // --- obtain h_t into shared memory ---
    if (t == 0) {
      for (int k = tid; k < HID; k += SCAN_THREADS) sh_h[k] = h0[k];
    } else {
      if (tid == 0) {
        const int target = NCTA * t;
        while (*(volatile int*)&g_counter < target) { }
      }
      __syncthreads();
      const volatile float* src = g_hbuf[t & 1];
      for (int k = tid; k < HID; k += SCAN_THREADS) sh_h[k] = src[k];
    }
    __syncthreads();

    // --- 4 dot products of length 1024, f32x2 packed ---
    ull acc2[4];
    #pragma unroll
    for (int g = 0; g < 4; ++g) acc2[g] = 0ULL;
    #pragma unroll
    for (int i = 0; i < 16; ++i) {
      ull hh = *(const ull*)(sh_h + 2 * (lane + 32 * i));
      #pragma unroll
      for (int g = 0; g < 4; ++g) fma2(acc2[g], wreg[g][i], hh);
    }
    float acc[4];
    #pragma unroll
    for (int g = 0; g < 4; ++g) {
      float lo, hi; upk2(acc2[g], lo, hi);
      acc[g] = lo + hi;
    }
    // butterfly reduce: every lane ends with the full sums
    #pragma unroll
    for (int off = 16; off > 0; off >>= 1)
      #pragma unroll
      for (int g = 0; g < 4; ++g)
        acc[g] += __shfl_xor_sync(0xffffffffu, acc[g], off);

    float xg0 = __shfl_sync(0xffffffffu, xgv, 0);
    float xg1 = __shfl_sync(0xffffffffu, xgv, 1);
    float xg2 = __shfl_sync(0xffffffffu, xgv, 2);
    float xg3 = __shfl_sync(0xffffffffu, xgv, 3);

    // gate order i, f, g, o (PyTorch)
    float iv = sigm(acc[0] + xg0);
    float fv = sigm(acc[1] + xg1);
    float gv = tanh_(acc[2] + xg2);
    float ov = sigm(acc[3] + xg3);
    c = fv * c + iv * gv;
    float hn = ov * tanh_(c);

    if (lane == 0)
      *(volatile float*)&g_hbuf[(t + 1) & 1][j] = hn;
    __syncthreads();
    if (tid == 0) {
      __threadfence();
      atomicAdd(&g_counter, 1);
    }
  }
}

// ==============================================================================
// Kernel 3: log_softmax over the final hidden state (in g_hbuf[0] after 4096
// steps). One CTA, 1024 threads.
// ==============================================================================
__global__ void lsm_kernel(float* __restrict__ out)
{
  const int tid  = threadIdx.x;
  const int lane = tid & 31;
  const int w    = tid >> 5;
  __shared__ float red[32];
  __shared__ float bcast[2];

  float v = g_hbuf[0][tid];

  // max reduction
  float m = v;
  #pragma unroll
  for (int o = 16; o > 0; o >>= 1) m = fmaxf(m, __shfl_xor_sync(0xffffffffu, m, o));
  if (lane == 0) red[w] = m;
  __syncthreads();
  if (tid < 32) {
    float x = red[tid];
    #pragma unroll
    for (int o = 16; o > 0; o >>= 1) x = fmaxf(x, __shfl_xor_sync(0xffffffffu, x, o));
    if (tid == 0) bcast[0] = x;
  }
  __syncthreads();
  m = bcast[0];

  // sum of exp
  float e = __expf(v - m);
  float s = e;
  #pragma unroll
  for (int o = 16; o > 0; o >>= 1) s += __shfl_xor_sync(0xffffffffu, s, o);
  if (lane == 0) red[w] = s;
  __syncthreads();
  if (tid < 32) {
    float x = red[tid];
    #pragma unroll
    for (int o = 16; o > 0; o >>= 1) x += __shfl_xor_sync(0xffffffffu, x, o);
    if (tid == 0) bcast[1] = logf(x);
  }
  __syncthreads();

  out[tid] = (v - m) - bcast[1];
}

// ==============================================================================
extern "C" void kernel_launch(void* const* d_in, const int* in_sizes, int n_in,
                              void* d_out, int out_size)
{
  const int*   inputs = (const int*)  d_in[0];
  const float* emb    = (const float*)d_in[1];
  const float* W_ih   = (const float*)d_in[2];
  const float* W_hh   = (const float*)d_in[3];
  const float* b_ih   = (const float*)d_in[4];
  const float* b_hh   = (const float*)d_in[5];
  const float* h0     = (const float*)d_in[6];
  const float* c0     = (const float*)d_in[7];
  float* out = (float*)d_out;

  dim3 grid(G4 / 128, SEQ / 128);
  xg_gemm<<<grid, 256>>>(inputs, emb, W_ih, b_ih, b_hh);
  lstm_scan<<<NCTA, SCAN_THREADS>>>(W_hh, h0, c0);
  lsm_kernel<<<1, HID>>>(out);
}

// round 3
// speedup vs baseline: 1.0481x; 1.0481x over previous
#include <cuda_runtime.h>
#include <cstdint>
#include <cstddef>

#define SEQ  4096
#define HID  1024
#define G4   4096
#define NCTA 128
#define SCAN_THREADS 256

typedef unsigned long long ull;

// ---------------- persistent device scratch (static: allocation-free) ----------
__device__ float g_xg[(size_t)SEQ * G4];   // 64 MB: precomputed input-side gates
__device__ float g_hbuf[2][HID];           // double-buffered hidden state
__device__ int   g_counter;                // grid barrier counter (reset by GEMM)

// ---------------- packed f32x2 helpers ----------------------------------------
__device__ __forceinline__ ull pk2(float x, float y) {
  ull r; asm("mov.b64 %0, {%1, %2};" : "=l"(r) : "f"(x), "f"(y)); return r;
}
__device__ __forceinline__ void upk2(ull v, float& x, float& y) {
  asm("mov.b64 {%0, %1}, %2;" : "=f"(x), "=f"(y) : "l"(v));
}
__device__ __forceinline__ void fma2(ull& d, ull a, ull b) {
  asm("fma.rn.f32x2 %0, %1, %2, %0;" : "+l"(d) : "l"(a), "l"(b));
}

__device__ __forceinline__ float sigm(float x) {
  return __fdividef(1.0f, 1.0f + __expf(-x));
}
__device__ __forceinline__ float tanh_(float x) {
  float e = __expf(2.0f * x);
  return 1.0f - __fdividef(2.0f, e + 1.0f);
}

// acquire-load of the barrier counter
__device__ __forceinline__ int ld_acq(const int* p) {
  int v;
  asm volatile("ld.acquire.gpu.global.s32 %0, [%1];" : "=r"(v) : "l"(p) : "memory");
  return v;
}
// release reduction (no return) on the barrier counter — single SASS op,
// no CCTL.IVALL (unlike __threadfence + atomicAdd)
__device__ __forceinline__ void red_rel_add(int* p, int v) {
  asm volatile("red.release.gpu.global.add.s32 [%0], %1;" :: "l"(p), "r"(v) : "memory");
}

// ==============================================================================
// Kernel 1: xg[m][n] = sum_k emb[inputs[m]][k] * W_ih[n][k] + b_ih[n] + b_hh[n]
// 128x128 tile, BK=8, 256 threads, 8x8 micro-tile via fma.rn.f32x2.
// Also resets the scan barrier counter (stream-ordered before the scan).
// ==============================================================================
__global__ __launch_bounds__(256, 2) void xg_gemm(
    const int*   __restrict__ inputs,
    const float* __restrict__ emb,
    const float* __restrict__ Wih,
    const float* __restrict__ b_ih,
    const float* __restrict__ b_hh)
{
  if (blockIdx.x == 0 && blockIdx.y == 0 && threadIdx.x == 0) g_counter = 0;

  __shared__ __align__(16) float As[8][128];
  __shared__ __align__(16) float Bs[8][128];
  __shared__ int idx[128];

  const int tid = threadIdx.x;
  const int m0 = blockIdx.y << 7;
  const int n0 = blockIdx.x << 7;

  if (tid < 128) idx[tid] = inputs[m0 + tid];
  __syncthreads();

  const int lr = tid >> 1;           // 0..127 row for cooperative loads
  const int lk = (tid & 1) << 2;     // k offset 0 or 4
  const int tx = tid & 15;           // micro-tile col group
  const int ty = tid >> 4;           // micro-tile row group

  const float* aptr = emb + (size_t)idx[lr] * 1024 + lk;
  const float* bptr = Wih + (size_t)(n0 + lr) * 1024 + lk;

  ull acc2[8][4];
  #pragma unroll
  for (int i = 0; i < 8; ++i)
    #pragma unroll
    for (int p = 0; p < 4; ++p) acc2[i][p] = 0ULL;

  for (int k0 = 0; k0 < 1024; k0 += 8) {
    float4 av = *(const float4*)(aptr + k0);
    float4 bv = *(const float4*)(bptr + k0);
    __syncthreads();
    As[lk + 0][lr] = av.x; As[lk + 1][lr] = av.y;
    As[lk + 2][lr] = av.z; As[lk + 3][lr] = av.w;
    Bs[lk + 0][lr] = bv.x; Bs[lk + 1][lr] = bv.y;
    Bs[lk + 2][lr] = bv.z; Bs[lk + 3][lr] = bv.w;
    __syncthreads();

    #pragma unroll
    for (int kk = 0; kk < 8; ++kk) {
      float4 a0 = *(const float4*)&As[kk][ty << 3];
      float4 a1 = *(const float4*)&As[kk][(ty << 3) + 4];
      float4 b0 = *(const float4*)&Bs[kk][tx << 3];
      float4 b1 = *(const float4*)&Bs[kk][(tx << 3) + 4];
      ull bq[4];
      bq[0] = pk2(b0.x, b0.y); bq[1] = pk2(b0.z, b0.w);
      bq[2] = pk2(b1.x, b1.y); bq[3] = pk2(b1.z, b1.w);
      float a[8] = {a0.x, a0.y, a0.z, a0.w, a1.x, a1.y, a1.z, a1.w};
      #pragma unroll
      for (int i = 0; i < 8; ++i) {
        ull ad = pk2(a[i], a[i]);
        #pragma unroll
        for (int p = 0; p < 4; ++p) fma2(acc2[i][p], ad, bq[p]);
      }
    }
  }

  // epilogue: + (b_ih + b_hh), store float4s
  float bias[8];
  #pragma unroll
  for (int p = 0; p < 8; ++p) {
    int n = n0 + (tx << 3) + p;
    bias[p] = b_ih[n] + b_hh[n];
  }
  #pragma unroll
  for (int i = 0; i < 8; ++i) {
    float c[8];
    #pragma unroll
    for (int p = 0; p < 4; ++p) upk2(acc2[i][p], c[2 * p], c[2 * p + 1]);
    #pragma unroll
    for (int p = 0; p < 8; ++p) c[p] += bias[p];
    int m = m0 + (ty << 3) + i;
    float* outp = g_xg + (size_t)m * G4 + n0 + (tx << 3);
    *(float4*)(outp)     = make_float4(c[0], c[1], c[2], c[3]);
    *(float4*)(outp + 4) = make_float4(c[4], c[5], c[6], c[7]);
  }
}

// ==============================================================================
// Kernel 2: persistent LSTM scan. 128 CTAs (all co-resident), 256 threads each.
// CTA b owns h columns j in [8b, 8b+8): 32 rows of W_hh register-resident.
// Warp w handles j = 8b + w: rows {j, j+1024, j+2048, j+3072}.
// Per lane: 16 f32x2 weight pairs per row (cols 2*(lane+32i), +1).
// Sync: acquire-poll on g_counter / release-red increment. No volatile, no
// threadfence (avoids per-step CCTL.IVALL L1 flush).
// ==============================================================================
__global__ __launch_bounds__(SCAN_THREADS, 1) void lstm_scan(
    const float* __restrict__ W_hh,
    const float* __restrict__ h0,
    const float* __restrict__ c0)
{
  const int tid  = threadIdx.x;
  const int lane = tid & 31;
  const int w    = tid >> 5;                  // warp 0..7
  const int j    = (blockIdx.x << 3) + w;     // 0..1023

  __shared__ __align__(16) float sh_h[HID];

  // load this thread's 128 weights (as 64 f32x2 pairs) into registers
  ull wreg[4][16];
  #pragma unroll
  for (int g = 0; g < 4; ++g) {
    const float* wp = W_hh + (size_t)(j + (g << 10)) * HID;
    #pragma unroll
    for (int i = 0; i < 16; ++i) {
      float2 v = *(const float2*)(wp + 2 * (lane + 32 * i));
      wreg[g][i] = pk2(v.x, v.y);
    }
  }
  float c = c0[j];   // replicated across lanes (identical updates keep it consistent)

  for (int t = 0; t < SEQ; ++t) {
    // prefetch this step's input-side gate values early (hides DRAM/L2 latency
    // behind the barrier wait)
    float xgv = 0.0f;
    if (lane < 4) xgv = __ldg(g_xg + (size_t)t * G4 + j + (lane << 10));

    // --- obtain h_t into shared memory ---
    if (t == 0) {
      float4 hv = ((const float4*)h0)[tid];
      ((float4*)sh_h)[tid] = hv;
    } else {
      if (tid == 0) {
        const int target = NCTA * t;
        while (ld_acq(&g_counter) < target) { }
      }
      __syncthreads();
      // plain (weak) vector load — ordered by the acquire above via the barrier
      float4 hv = ((const float4*)g_hbuf[t & 1])[tid];
      ((float4*)sh_h)[tid] = hv;
    }
    __syncthreads();

    // --- 4 dot products of length 1024, f32x2 packed ---
    ull acc2[4];
    #pragma unroll
    for (int g = 0; g < 4; ++g) acc2[g] = 0ULL;
    #pragma unroll
    for (int i = 0; i < 16; ++i) {
      ull hh = *(const ull*)(sh_h + 2 * (lane + 32 * i));
      #pragma unroll
      for (int g = 0; g < 4; ++g) fma2(acc2[g], wreg[g][i], hh);
    }
    float acc[4];
    #pragma unroll
    for (int g = 0; g < 4; ++g) {
      float lo, hi; upk2(acc2[g], lo, hi);
      acc[g] = lo + hi;
    }
    // butterfly reduce: every lane ends with the full sums
    #pragma unroll
    for (int off = 16; off > 0; off >>= 1)
      #pragma unroll
      for (int g = 0; g < 4; ++g)
        acc[g] += __shfl_xor_sync(0xffffffffu, acc[g], off);

    float xg0 = __shfl_sync(0xffffffffu, xgv, 0);
    float xg1 = __shfl_sync(0xffffffffu, xgv, 1);
    float xg2 = __shfl_sync(0xffffffffu, xgv, 2);
    float xg3 = __shfl_sync(0xffffffffu, xgv, 3);

    // gate order i, f, g, o (PyTorch)
    float iv = sigm(acc[0] + xg0);
    float fv = sigm(acc[1] + xg1);
    float gv = tanh_(acc[2] + xg2);
    float ov = sigm(acc[3] + xg3);
    c = fv * c + iv * gv;
    float hn = ov * tanh_(c);

    if (lane == 0)
      g_hbuf[(t + 1) & 1][j] = hn;   // plain store; release-red below publishes it
    __syncthreads();                  // all warps' h-stores precede the release
    if (tid == 0)
      red_rel_add(&g_counter, 1);
  }
}

// ==============================================================================
// Kernel 3: log_softmax over the final hidden state (in g_hbuf[0] after 4096
// steps). One CTA, 1024 threads.
// ==============================================================================
__global__ void lsm_kernel(float* __restrict__ out)
{
  const int tid  = threadIdx.x;
  const int lane = tid & 31;
  const int w    = tid >> 5;
  __shared__ float red[32];
  __shared__ float bcast[2];

  float v = g_hbuf[0][tid];

  // max reduction
  float m = v;
  #pragma unroll
  for (int o = 16; o > 0; o >>= 1) m = fmaxf(m, __shfl_xor_sync(0xffffffffu, m, o));
  if (lane == 0) red[w] = m;
  __syncthreads();
  if (tid < 32) {
    float x = red[tid];
    #pragma unroll
    for (int o = 16; o > 0; o >>= 1) x = fmaxf(x, __shfl_xor_sync(0xffffffffu, x, o));
    if (tid == 0) bcast[0] = x;
  }
  __syncthreads();
  m = bcast[0];

  // sum of exp
  float e = __expf(v - m);
  float s = e;
  #pragma unroll
  for (int o = 16; o > 0; o >>= 1) s += __shfl_xor_sync(0xffffffffu, s, o);
  if (lane == 0) red[w] = s;
  __syncthreads();
  if (tid < 32) {
    float x = red[tid];
    #pragma unroll
    for (int o = 16; o > 0; o >>= 1) x += __shfl_xor_sync(0xffffffffu, x, o);
    if (tid == 0) bcast[1] = logf(x);
  }
  __syncthreads();

  out[tid] = (v - m) - bcast[1];
}

// ==============================================================================
extern "C" void kernel_launch(void* const* d_in, const int* in_sizes, int n_in,
                              void* d_out, int out_size)
{
  const int*   inputs = (const int*)  d_in[0];
  const float* emb    = (const float*)d_in[1];
  const float* W_ih   = (const float*)d_in[2];
  const float* W_hh   = (const float*)d_in[3];
  const float* b_ih   = (const float*)d_in[4];
  const float* b_hh   = (const float*)d_in[5];
  const float* h0     = (const float*)d_in[6];
  const float* c0     = (const float*)d_in[7];
  float* out = (float*)d_out;

  dim3 grid(G4 / 128, SEQ / 128);
  xg_gemm<<<grid, 256>>>(inputs, emb, W_ih, b_ih, b_hh);
  lstm_scan<<<NCTA, SCAN_THREADS>>>(W_hh, h0, c0);
  lsm_kernel<<<1, HID>>>(out);
}

// round 6
// speedup vs baseline: 1.1737x; 1.1198x over previous
#include <cuda_runtime.h>
#include <cstdint>
#include <cstddef>

#define SEQ  4096
#define HID  1024
#define G4   4096
#define NCTA 128
#define SCAN_THREADS 256

typedef unsigned long long ull;

// ---------------- persistent device scratch (static: allocation-free) ----------
__device__ float g_xg[(size_t)SEQ * G4];   // 64 MB: precomputed input-side gates
__device__ float g_hbuf[2][HID];           // double-buffered hidden state
// per-CTA progress flags, padded to 32B so each lives in its own L2 sector
// (no per-address atomic-ALU serialization, no line false-sharing)
__device__ int   g_flag[NCTA * 8];

// ---------------- packed f32x2 helpers ----------------------------------------
__device__ __forceinline__ ull pk2(float x, float y) {
  ull r; asm("mov.b64 %0, {%1, %2};" : "=l"(r) : "f"(x), "f"(y)); return r;
}
__device__ __forceinline__ void upk2(ull v, float& x, float& y) {
  asm("mov.b64 {%0, %1}, %2;" : "=f"(x), "=f"(y) : "l"(v));
}
__device__ __forceinline__ void fma2(ull& d, ull a, ull b) {
  asm("fma.rn.f32x2 %0, %1, %2, %0;" : "+l"(d) : "l"(a), "l"(b));
}

__device__ __forceinline__ float sigm(float x) {
  return __fdividef(1.0f, 1.0f + __expf(-x));
}
__device__ __forceinline__ float tanh_(float x) {
  float e = __expf(2.0f * x);
  return 1.0f - __fdividef(2.0f, e + 1.0f);
}

__device__ __forceinline__ int ld_acq(const int* p) {
  int v;
  asm volatile("ld.acquire.gpu.global.s32 %0, [%1];" : "=r"(v) : "l"(p) : "memory");
  return v;
}
__device__ __forceinline__ void st_rel(int* p, int v) {
  asm volatile("st.release.gpu.global.s32 [%0], %1;" :: "l"(p), "r"(v) : "memory");
}

// ==============================================================================
// Kernel 1: xg[m][n] = sum_k emb[inputs[m]][k] * W_ih[n][k] + b_ih[n] + b_hh[n]
// 128x128 tile, BK=8, 256 threads, 8x8 micro-tile via fma.rn.f32x2.
// Also resets the scan progress flags (stream-ordered before the scan).
// ==============================================================================
__global__ __launch_bounds__(256, 2) void xg_gemm(
    const int*   __restrict__ inputs,
    const float* __restrict__ emb,
    const float* __restrict__ Wih,
    const float* __restrict__ b_ih,
    const float* __restrict__ b_hh)
{
  if (blockIdx.x == 0 && blockIdx.y == 0) {
    for (int i = threadIdx.x; i < NCTA * 8; i += 256) g_flag[i] = 0;
  }

  __shared__ __align__(16) float As[8][128];
  __shared__ __align__(16) float Bs[8][128];
  __shared__ int idx[128];

  const int tid = threadIdx.x;
  const int m0 = blockIdx.y << 7;
  const int n0 = blockIdx.x << 7;

  if (tid < 128) idx[tid] = inputs[m0 + tid];
  __syncthreads();

  const int lr = tid >> 1;           // 0..127 row for cooperative loads
  const int lk = (tid & 1) << 2;     // k offset 0 or 4
  const int tx = tid & 15;           // micro-tile col group
  const int ty = tid >> 4;           // micro-tile row group

  const float* aptr = emb + (size_t)idx[lr] * 1024 + lk;
  const float* bptr = Wih + (size_t)(n0 + lr) * 1024 + lk;

  ull acc2[8][4];
  #pragma unroll
  for (int i = 0; i < 8; ++i)
    #pragma unroll
    for (int p = 0; p < 4; ++p) acc2[i][p] = 0ULL;

  for (int k0 = 0; k0 < 1024; k0 += 8) {
    float4 av = *(const float4*)(aptr + k0);
    float4 bv = *(const float4*)(bptr + k0);
    __syncthreads();
    As[lk + 0][lr] = av.x; As[lk + 1][lr] = av.y;
    As[lk + 2][lr] = av.z; As[lk + 3][lr] = av.w;
    Bs[lk + 0][lr] = bv.x; Bs[lk + 1][lr] = bv.y;
    Bs[lk + 2][lr] = bv.z; Bs[lk + 3][lr] = bv.w;
    __syncthreads();

    #pragma unroll
    for (int kk = 0; kk < 8; ++kk) {
      float4 a0 = *(const float4*)&As[kk][ty << 3];
      float4 a1 = *(const float4*)&As[kk][(ty << 3) + 4];
      float4 b0 = *(const float4*)&Bs[kk][tx << 3];
      float4 b1 = *(const float4*)&Bs[kk][(tx << 3) + 4];
      ull bq[4];
      bq[0] = pk2(b0.x, b0.y); bq[1] = pk2(b0.z, b0.w);
      bq[2] = pk2(b1.x, b1.y); bq[3] = pk2(b1.z, b1.w);
      float a[8] = {a0.x, a0.y, a0.z, a0.w, a1.x, a1.y, a1.z, a1.w};
      #pragma unroll
      for (int i = 0; i < 8; ++i) {
        ull ad = pk2(a[i], a[i]);
        #pragma unroll
        for (int p = 0; p < 4; ++p) fma2(acc2[i][p], ad, bq[p]);
      }
    }
  }

  // epilogue: + (b_ih + b_hh), store float4s
  float bias[8];
  #pragma unroll
  for (int p = 0; p < 8; ++p) {
    int n = n0 + (tx << 3) + p;
    bias[p] = b_ih[n] + b_hh[n];
  }
  #pragma unroll
  for (int i = 0; i < 8; ++i) {
    float c[8];
    #pragma unroll
    for (int p = 0; p < 4; ++p) upk2(acc2[i][p], c[2 * p], c[2 * p + 1]);
    #pragma unroll
    for (int p = 0; p < 8; ++p) c[p] += bias[p];
    int m = m0 + (ty << 3) + i;
    float* outp = g_xg + (size_t)m * G4 + n0 + (tx << 3);
    *(float4*)(outp)     = make_float4(c[0], c[1], c[2], c[3]);
    *(float4*)(outp + 4) = make_float4(c[4], c[5], c[6], c[7]);
  }
}

// ==============================================================================
// Kernel 2: persistent LSTM scan. 128 CTAs (all co-resident), 256 threads each.
// CTA b owns h columns j in [8b, 8b+8): 32 rows of W_hh register-resident.
// Warp w handles j = 8b + w: rows {j, j+1024, j+2048, j+3072}.
// Per lane: 16 f32x2 weight pairs per row (cols 2*(lane+32i), +1).
//
// Barrier: per-CTA padded release flags (st.release of step number) + 128
// PARALLEL ld.acquire spins (threads 0..127, one flag each). No shared atomic
// counter -> no per-address LTS atomic-ALU serialization (which cost ~3400
// cyc/step in the previous version).
// ==============================================================================
__global__ __launch_bounds__(SCAN_THREADS, 1) void lstm_scan(
    const float* __restrict__ W_hh,
    const float* __restrict__ h0,
    const float* __restrict__ c0)
{
  const int tid  = threadIdx.x;
  const int lane = tid & 31;
  const int w    = tid >> 5;                  // warp 0..7
  const int j    = (blockIdx.x << 3) + w;     // 0..1023

  __shared__ __align__(16) float sh_h[HID];

  // load this thread's 128 weights (as 64 f32x2 pairs) into registers
  ull wreg[4][16];
  #pragma unroll
  for (int g = 0; g < 4; ++g) {
    const float* wp = W_hh + (size_t)(j + (g << 10)) * HID;
    #pragma unroll
    for (int i = 0; i < 16; ++i) {
      float2 v = *(const float2*)(wp + 2 * (lane + 32 * i));
      wreg[g][i] = pk2(v.x, v.y);
    }
  }
  float c = c0[j];   // replicated across lanes (identical updates keep it consistent)

  int* my_flag = &g_flag[blockIdx.x << 3];
  const int* spin_flag = &g_flag[(tid & (NCTA - 1)) << 3];

  for (int t = 0; t < SEQ; ++t) {
    // prefetch this step's input-side gate values early (hides DRAM/L2 latency
    // behind the barrier wait)
    float xgv = 0.0f;
    if (lane < 4) xgv = __ldg(g_xg + (size_t)t * G4 + j + (lane << 10));

    // --- obtain h_t into shared memory ---
    if (t == 0) {
      ((float4*)sh_h)[tid] = ((const float4*)h0)[tid];
    } else {
      // wait for all producers: threads 0..127 each spin on one CTA's flag
      if (tid < NCTA) {
        while (ld_acq(spin_flag) < t) { }
      }
      __syncthreads();
      // plain (weak) vector load — ordered by the acquires above + barrier
      ((float4*)sh_h)[tid] = ((const float4*)g_hbuf[t & 1])[tid];
    }
    __syncthreads();

    // --- 4 dot products of length 1024, f32x2 packed ---
    ull acc2[4];
    #pragma unroll
    for (int g = 0; g < 4; ++g) acc2[g] = 0ULL;
    #pragma unroll
    for (int i = 0; i < 16; ++i) {
      ull hh = *(const ull*)(sh_h + 2 * (lane + 32 * i));
      #pragma unroll
      for (int g = 0; g < 4; ++g) fma2(acc2[g], wreg[g][i], hh);
    }
    float acc[4];
    #pragma unroll
    for (int g = 0; g < 4; ++g) {
      float lo, hi; upk2(acc2[g], lo, hi);
      acc[g] = lo + hi;
    }
    // butterfly reduce: every lane ends with the full sums
    #pragma unroll
    for (int off = 16; off > 0; off >>= 1)
      #pragma unroll
      for (int g = 0; g < 4; ++g)
        acc[g] += __shfl_xor_sync(0xffffffffu, acc[g], off);

    float xg0 = __shfl_sync(0xffffffffu, xgv, 0);
    float xg1 = __shfl_sync(0xffffffffu, xgv, 1);
    float xg2 = __shfl_sync(0xffffffffu, xgv, 2);
    float xg3 = __shfl_sync(0xffffffffu, xgv, 3);

    // gate order i, f, g, o (PyTorch)
    float iv = sigm(acc[0] + xg0);
    float fv = sigm(acc[1] + xg1);
    float gv = tanh_(acc[2] + xg2);
    float ov = sigm(acc[3] + xg3);
    c = fv * c + iv * gv;
    float hn = ov * tanh_(c);

    if (lane == 0)
      g_hbuf[(t + 1) & 1][j] = hn;   // weak store; the release below publishes it
    __syncthreads();                  // all 8 warps' h-stores precede the release
    if (tid == 0)
      st_rel(my_flag, t + 1);         // one plain release store per CTA per step
  }
}

// ==============================================================================
// Kernel 3: log_softmax over the final hidden state (in g_hbuf[0] after 4096
// steps). One CTA, 1024 threads.
// ==============================================================================
__global__ void lsm_kernel(float* __restrict__ out)
{
  const int tid  = threadIdx.x;
  const int lane = tid & 31;
  const int w    = tid >> 5;
  __shared__ float red[32];
  __shared__ float bcast[2];

  float v = g_hbuf[0][tid];

  // max reduction
  float m = v;
  #pragma unroll
  for (int o = 16; o > 0; o >>= 1) m = fmaxf(m, __shfl_xor_sync(0xffffffffu, m, o));
  if (lane == 0) red[w] = m;
  __syncthreads();
  if (tid < 32) {
    float x = red[tid];
    #pragma unroll
    for (int o = 16; o > 0; o >>= 1) x = fmaxf(x, __shfl_xor_sync(0xffffffffu, x, o));
    if (tid == 0) bcast[0] = x;
  }
  __syncthreads();
  m = bcast[0];

  // sum of exp
  float e = __expf(v - m);
  float s = e;
  #pragma unroll
  for (int o = 16; o > 0; o >>= 1) s += __shfl_xor_sync(0xffffffffu, s, o);
  if (lane == 0) red[w] = s;
  __syncthreads();
  if (tid < 32) {
    float x = red[tid];
    #pragma unroll
    for (int o = 16; o > 0; o >>= 1) x += __shfl_xor_sync(0xffffffffu, x, o);
    if (tid == 0) bcast[1] = logf(x);
  }
  __syncthreads();

  out[tid] = (v - m) - bcast[1];
}

// ==============================================================================
extern "C" void kernel_launch(void* const* d_in, const int* in_sizes, int n_in,
                              void* d_out, int out_size)
{
  const int*   inputs = (const int*)  d_in[0];
  const float* emb    = (const float*)d_in[1];
  const float* W_ih   = (const float*)d_in[2];
  const float* W_hh   = (const float*)d_in[3];
  const float* b_ih   = (const float*)d_in[4];
  const float* b_hh   = (const float*)d_in[5];
  const float* h0     = (const float*)d_in[6];
  const float* c0     = (const float*)d_in[7];
  float* out = (float*)d_out;

  dim3 grid(G4 / 128, SEQ / 128);
  xg_gemm<<<grid, 256>>>(inputs, emb, W_ih, b_ih, b_hh);
  lstm_scan<<<NCTA, SCAN_THREADS>>>(W_hh, h0, c0);
  lsm_kernel<<<1, HID>>>(out);
}

// round 7
// speedup vs baseline: 1.6740x; 1.4263x over previous
#include <cuda_runtime.h>
#include <cstdint>
#include <cstddef>

#define SEQ  4096
#define HID  1024
#define G4   4096
#define NCTA 128
#define SCAN_THREADS 256

typedef unsigned long long ull;

// ---------------- persistent device scratch (static: allocation-free) ----------
__device__ float g_xg[(size_t)SEQ * G4];   // 64 MB: precomputed input-side gates
// Tagged h records: (h value, step tag) packed in 8B -> single-copy atomic.
// Double-buffered by step parity. Consumers read 16B (2 records) at a time.
__device__ __align__(16) uint2 g_hrec[2][HID];   // 16 KB

// ---------------- packed f32x2 helpers ----------------------------------------
__device__ __forceinline__ ull pk2(float x, float y) {
  ull r; asm("mov.b64 %0, {%1, %2};" : "=l"(r) : "f"(x), "f"(y)); return r;
}
__device__ __forceinline__ void upk2(ull v, float& x, float& y) {
  asm("mov.b64 {%0, %1}, %2;" : "=f"(x), "=f"(y) : "l"(v));
}
__device__ __forceinline__ void fma2(ull& d, ull a, ull b) {
  asm("fma.rn.f32x2 %0, %1, %2, %0;" : "+l"(d) : "l"(a), "l"(b));
}

__device__ __forceinline__ float sigm(float x) {
  return __fdividef(1.0f, 1.0f + __expf(-x));
}
__device__ __forceinline__ float tanh_(float x) {
  float e = __expf(2.0f * x);
  return 1.0f - __fdividef(2.0f, e + 1.0f);
}

// strong (L2-coherent) 16B load: returns 2 records (h,tag,h,tag)
__device__ __forceinline__ uint4 ld_rec2(const uint2* p) {
  uint4 v;
  asm volatile("ld.relaxed.gpu.global.v4.b32 {%0,%1,%2,%3}, [%4];"
               : "=r"(v.x), "=r"(v.y), "=r"(v.z), "=r"(v.w) : "l"(p) : "memory");
  return v;
}
// strong 8B store: one record (h, tag) — tag travels with the payload
__device__ __forceinline__ void st_rec(uint2* p, float h, unsigned tag) {
  asm volatile("st.relaxed.gpu.global.v2.b32 [%0], {%1,%2};"
               :: "l"(p), "r"(__float_as_uint(h)), "r"(tag) : "memory");
}

// ==============================================================================
// Kernel 1: xg[m][n] = sum_k emb[inputs[m]][k] * W_ih[n][k] + b_ih[n] + b_hh[n]
// 128x128 tile, BK=8, 256 threads, 8x8 micro-tile via fma.rn.f32x2, 1-deep
// register prefetch pipeline (hide global load latency under compute).
// Also resets the scan h-records (stream-ordered before the scan).
// ==============================================================================
__global__ __launch_bounds__(256, 2) void xg_gemm(
    const int*   __restrict__ inputs,
    const float* __restrict__ emb,
    const float* __restrict__ Wih,
    const float* __restrict__ b_ih,
    const float* __restrict__ b_hh)
{
  if (blockIdx.x == 0 && blockIdx.y == 0) {
    for (int i = threadIdx.x; i < 2 * HID; i += 256)
      ((uint2*)g_hrec)[i] = make_uint2(0u, 0u);
  }

  __shared__ __align__(16) float As[8][128];
  __shared__ __align__(16) float Bs[8][128];
  __shared__ int idx[128];

  const int tid = threadIdx.x;
  const int m0 = blockIdx.y << 7;
  const int n0 = blockIdx.x << 7;

  if (tid < 128) idx[tid] = inputs[m0 + tid];
  __syncthreads();

  const int lr = tid >> 1;           // 0..127 row for cooperative loads
  const int lk = (tid & 1) << 2;     // k offset 0 or 4
  const int tx = tid & 15;           // micro-tile col group
  const int ty = tid >> 4;           // micro-tile row group

  const float* aptr = emb + (size_t)idx[lr] * 1024 + lk;
  const float* bptr = Wih + (size_t)(n0 + lr) * 1024 + lk;

  ull acc2[8][4];
  #pragma unroll
  for (int i = 0; i < 8; ++i)
    #pragma unroll
    for (int p = 0; p < 4; ++p) acc2[i][p] = 0ULL;

  // pipeline prologue: first K-tile loads
  float4 av = *(const float4*)(aptr);
  float4 bv = *(const float4*)(bptr);

  for (int k0 = 0; k0 < 1024; k0 += 8) {
    __syncthreads();                 // previous tile fully consumed
    As[lk + 0][lr] = av.x; As[lk + 1][lr] = av.y;
    As[lk + 2][lr] = av.z; As[lk + 3][lr] = av.w;
    Bs[lk + 0][lr] = bv.x; Bs[lk + 1][lr] = bv.y;
    Bs[lk + 2][lr] = bv.z; Bs[lk + 3][lr] = bv.w;
    __syncthreads();

    // prefetch next K-tile while computing this one
    const int kn = (k0 + 8 < 1024) ? (k0 + 8) : 0;
    av = *(const float4*)(aptr + kn);
    bv = *(const float4*)(bptr + kn);

    #pragma unroll
    for (int kk = 0; kk < 8; ++kk) {
      float4 a0 = *(const float4*)&As[kk][ty << 3];
      float4 a1 = *(const float4*)&As[kk][(ty << 3) + 4];
      float4 b0 = *(const float4*)&Bs[kk][tx << 3];
      float4 b1 = *(const float4*)&Bs[kk][(tx << 3) + 4];
      ull bq[4];
      bq[0] = pk2(b0.x, b0.y); bq[1] = pk2(b0.z, b0.w);
      bq[2] = pk2(b1.x, b1.y); bq[3] = pk2(b1.z, b1.w);
      float a[8] = {a0.x, a0.y, a0.z, a0.w, a1.x, a1.y, a1.z, a1.w};
      #pragma unroll
      for (int i = 0; i < 8; ++i) {
        ull ad = pk2(a[i], a[i]);
        #pragma unroll
        for (int p = 0; p < 4; ++p) fma2(acc2[i][p], ad, bq[p]);
      }
    }
  }

  // epilogue: + (b_ih + b_hh), store float4s
  float bias[8];
  #pragma unroll
  for (int p = 0; p < 8; ++p) {
    int n = n0 + (tx << 3) + p;
    bias[p] = b_ih[n] + b_hh[n];
  }
  #pragma unroll
  for (int i = 0; i < 8; ++i) {
    float c[8];
    #pragma unroll
    for (int p = 0; p < 4; ++p) upk2(acc2[i][p], c[2 * p], c[2 * p + 1]);
    #pragma unroll
    for (int p = 0; p < 8; ++p) c[p] += bias[p];
    int m = m0 + (ty << 3) + i;
    float* outp = g_xg + (size_t)m * G4 + n0 + (tx << 3);
    *(float4*)(outp)     = make_float4(c[0], c[1], c[2], c[3]);
    *(float4*)(outp + 4) = make_float4(c[4], c[5], c[6], c[7]);
  }
}

// ==============================================================================
// Kernel 2: persistent LSTM scan. 128 CTAs (all co-resident), 256 threads each.
// CTA b owns h columns j in [8b, 8b+8): 32 rows of W_hh register-resident.
// Warp w handles j = 8b + w: rows {j, j+1024, j+2048, j+3072}.
//
// Sync: tagged h records. Producer warp publishes (h_j, t+1) as ONE 8B strong
// store the moment its h is ready (no end-of-step CTA barrier). Consumers spin
// on 16B strong loads that return tag AND payload together — one L2 round trip
// delivers both synchronization and data (the old design needed two).
// Double-buffered by step parity; single-copy atomicity of aligned 8B/16B
// strong accesses makes fences unnecessary.
// ==============================================================================
__global__ __launch_bounds__(SCAN_THREADS, 1) void lstm_scan(
    const float* __restrict__ W_hh,
    const float* __restrict__ h0,
    const float* __restrict__ c0)
{
  const int tid  = threadIdx.x;
  const int lane = tid & 31;
  const int w    = tid >> 5;                  // warp 0..7
  const int j    = (blockIdx.x << 3) + w;     // 0..1023

  __shared__ __align__(16) float sh_h[HID];

  // load this thread's 128 weights (as 64 f32x2 pairs) into registers
  ull wreg[4][16];
  #pragma unroll
  for (int g = 0; g < 4; ++g) {
    const float* wp = W_hh + (size_t)(j + (g << 10)) * HID;
    #pragma unroll
    for (int i = 0; i < 16; ++i) {
      float2 v = *(const float2*)(wp + 2 * (lane + 32 * i));
      wreg[g][i] = pk2(v.x, v.y);
    }
  }
  float c = c0[j];   // replicated across lanes (identical updates keep it consistent)

  for (int t = 0; t < SEQ; ++t) {
    // prefetch this step's input-side gate values early (hides DRAM/L2 latency
    // behind the record wait)
    float xgv = 0.0f;
    if (lane < 4) xgv = __ldg(g_xg + (size_t)t * G4 + j + (lane << 10));

    // --- obtain h_t into shared memory ---
    if (t == 0) {
      ((float4*)sh_h)[tid] = ((const float4*)h0)[tid];
    } else {
      // thread tid owns records 4*tid .. 4*tid+3 (two 16B loads, coalesced).
      // A 16B strong load returns (h,tag,h,tag) atomically: once tags >= t,
      // the h payloads in the same load are the current step's values.
      const uint2* rp = &g_hrec[t & 1][tid << 2];
      const unsigned tt = (unsigned)t;
      uint4 a, b;
      do {
        a = ld_rec2(rp);
        b = ld_rec2(rp + 2);
      } while (a.y < tt || a.w < tt || b.y < tt || b.w < tt);
      ((float4*)sh_h)[tid] = make_float4(__uint_as_float(a.x), __uint_as_float(a.z),
                                         __uint_as_float(b.x), __uint_as_float(b.z));
    }
    __syncthreads();

    // --- 4 dot products of length 1024, f32x2 packed ---
    ull acc2[4];
    #pragma unroll
    for (int g = 0; g < 4; ++g) acc2[g] = 0ULL;
    #pragma unroll
    for (int i = 0; i < 16; ++i) {
      ull hh = *(const ull*)(sh_h + 2 * (lane + 32 * i));
      #pragma unroll
      for (int g = 0; g < 4; ++g) fma2(acc2[g], wreg[g][i], hh);
    }
    float acc[4];
    #pragma unroll
    for (int g = 0; g < 4; ++g) {
      float lo, hi; upk2(acc2[g], lo, hi);
      acc[g] = lo + hi;
    }
    // butterfly reduce: every lane ends with the full sums
    #pragma unroll
    for (int off = 16; off > 0; off >>= 1)
      #pragma unroll
      for (int g = 0; g < 4; ++g)
        acc[g] += __shfl_xor_sync(0xffffffffu, acc[g], off);

    float xg0 = __shfl_sync(0xffffffffu, xgv, 0);
    float xg1 = __shfl_sync(0xffffffffu, xgv, 1);
    float xg2 = __shfl_sync(0xffffffffu, xgv, 2);
    float xg3 = __shfl_sync(0xffffffffu, xgv, 3);

    // gate order i, f, g, o (PyTorch)
    float iv = sigm(acc[0] + xg0);
    float fv = sigm(acc[1] + xg1);
    float gv = tanh_(acc[2] + xg2);
    float ov = sigm(acc[3] + xg3);
    c = fv * c + iv * gv;
    float hn = ov * tanh_(c);

    // publish immediately — per-warp, no CTA-wide barrier on the publish path
    if (lane == 0)
      st_rec(&g_hrec[(t + 1) & 1][j], hn, (unsigned)(t + 1));

    // protect sh_h against next step's overwrite while other warps still read it
    __syncthreads();
  }
}

// ==============================================================================
// Kernel 3: log_softmax over the final hidden state. After step t=4095 the
// final h was published with tag 4096 into g_hrec[0]. One CTA, 1024 threads.
// ==============================================================================
__global__ void lsm_kernel(float* __restrict__ out)
{
  const int tid  = threadIdx.x;
  const int lane = tid & 31;
  const int w    = tid >> 5;
  __shared__ float red[32];
  __shared__ float bcast[2];

  float v = __uint_as_float(g_hrec[0][tid].x);

  // max reduction
  float m = v;
  #pragma unroll
  for (int o = 16; o > 0; o >>= 1) m = fmaxf(m, __shfl_xor_sync(0xffffffffu, m, o));
  if (lane == 0) red[w] = m;
  __syncthreads();
  if (tid < 32) {
    float x = red[tid];
    #pragma unroll
    for (int o = 16; o > 0; o >>= 1) x = fmaxf(x, __shfl_xor_sync(0xffffffffu, x, o));
    if (tid == 0) bcast[0] = x;
  }
  __syncthreads();
  m = bcast[0];

  // sum of exp
  float e = __expf(v - m);
  float s = e;
  #pragma unroll
  for (int o = 16; o > 0; o >>= 1) s += __shfl_xor_sync(0xffffffffu, s, o);
  if (lane == 0) red[w] = s;
  __syncthreads();
  if (tid < 32) {
    float x = red[tid];
    #pragma unroll
    for (int o = 16; o > 0; o >>= 1) x += __shfl_xor_sync(0xffffffffu, x, o);
    if (tid == 0) bcast[1] = logf(x);
  }
  __syncthreads();

  out[tid] = (v - m) - bcast[1];
}

// ==============================================================================
extern "C" void kernel_launch(void* const* d_in, const int* in_sizes, int n_in,
                              void* d_out, int out_size)
{
  const int*   inputs = (const int*)  d_in[0];
  const float* emb    = (const float*)d_in[1];
  const float* W_ih   = (const float*)d_in[2];
  const float* W_hh   = (const float*)d_in[3];
  const float* b_ih   = (const float*)d_in[4];
  const float* b_hh   = (const float*)d_in[5];
  const float* h0     = (const float*)d_in[6];
  const float* c0     = (const float*)d_in[7];
  float* out = (float*)d_out;

  dim3 grid(G4 / 128, SEQ / 128);
  xg_gemm<<<grid, 256>>>(inputs, emb, W_ih, b_ih, b_hh);
  lstm_scan<<<NCTA, SCAN_THREADS>>>(W_hh, h0, c0);
  lsm_kernel<<<1, HID>>>(out);
}